// round 14
// baseline (speedup 1.0000x reference)
#include <cuda_runtime.h>
#include <cuda_fp16.h>
#include <cstdint>

// PolynomialMoE: N=1048576, DIM=2, HID=64, E=4, hard top-1.
// Output (float32): [ out (N*2) | router_logits (N*4) ]
//
// R14: N-split across warp pairs to break the 64-reg accumulator occupancy
// cap (R9-R13 all pinned at occ ~23%). Warp pair shares 32 token-rows; even
// warp does j 0..31, odd j 32..63 -> acc[2][4][4]=32 regs -> 3 CTAs/SM.
// Unlike the R10 M-split, B-fragment traffic per token is UNCHANGED (pair
// covers all nt once) and persistent CTAs keep weight staging amortized.
// L3 partials exchanged via 1KB smem. Math otherwise identical to R13.

typedef unsigned long long U64;

static constexpr int N_MAX = 1 << 20;
static constexpr int TILE  = 128;
static constexpr int NBLK  = 456;     // 3 CTAs/SM x 152 SMs

__device__ int d_cnt[4];
__device__ int d_perm[4 * N_MAX];
__device__ uint2    d_w2f[4 * 1024];  // [e][ks(4)][nt(8)][lane(32)]
__device__ uint32_t d_w1f[4 * 256];   // [e][nt(8)][lane(32)] (reg0 only)
__device__ uint2    d_w3f[4 * 128];   // [e][ks(4)][lane(32)]

// ---------------- helpers ----------------
__device__ __forceinline__ uint32_t packh2(float lo, float hi) {
    uint32_t r;
    asm("cvt.rn.f16x2.f32 %0, %1, %2;" : "=r"(r) : "f"(hi), "f"(lo));
    return r;
}
__device__ __forceinline__ uint32_t relu2(uint32_t v) {
    uint32_t r;
    asm("max.f16x2 %0, %1, %2;" : "=r"(r) : "r"(v), "r"(0u));
    return r;
}
__device__ __forceinline__ void mma_f16(float c[4], uint32_t a0, uint32_t a1,
                                        uint32_t a2, uint32_t a3,
                                        uint32_t b0, uint32_t b1) {
    asm volatile(
        "mma.sync.aligned.m16n8k16.row.col.f32.f16.f16.f32 "
        "{%0,%1,%2,%3}, {%4,%5,%6,%7}, {%8,%9}, {%0,%1,%2,%3};"
        : "+f"(c[0]), "+f"(c[1]), "+f"(c[2]), "+f"(c[3])
        : "r"(a0), "r"(a1), "r"(a2), "r"(a3), "r"(b0), "r"(b1));
}
__device__ __forceinline__ void mma_f16acc(uint32_t c[2], uint32_t a0,
                                           uint32_t a1, uint32_t b0) {
    asm volatile(
        "mma.sync.aligned.m16n8k16.row.col.f16.f16.f16.f16 "
        "{%0,%1}, {%2,%3,%4,%5}, {%6,%7}, {%0,%1};"
        : "+r"(c[0]), "+r"(c[1])
        : "r"(a0), "r"(a1), "r"(0u), "r"(0u), "r"(b0), "r"(0u));
}

// ---------------- Kernel 1: router (2 tok/thread) + fused weight prep ----
__global__ __launch_bounds__(256)
void router_kernel(const float* __restrict__ x,
                   const float* __restrict__ rW,
                   const float* __restrict__ rb,
                   const float* __restrict__ w1,
                   const float* __restrict__ b1,
                   const float* __restrict__ w2,
                   const float* __restrict__ w3,
                   float* __restrict__ out, int n)
{
    __shared__ int scnt[4], gbase[4];
    const int tid = threadIdx.x;
    if (tid < 4) scnt[tid] = 0;

    if (blockIdx.x < 4) {
        const int e = blockIdx.x;
        #pragma unroll
        for (int t = tid; t < 1024; t += 256) {
            const int ks = t >> 8, nt = (t >> 5) & 7, lane = t & 31;
            const int k0 = ks * 16 + (lane & 3) * 2;
            const int nn = nt * 8 + (lane >> 2);
            d_w2f[e * 1024 + t] = make_uint2(
                packh2(w2[e * 4096 + k0 * 64 + nn],
                       w2[e * 4096 + (k0 + 1) * 64 + nn]),
                packh2(w2[e * 4096 + (k0 + 8) * 64 + nn],
                       w2[e * 4096 + (k0 + 9) * 64 + nn]));
        }
    } else if (blockIdx.x < 8) {
        const int e = blockIdx.x - 4;
        {   // w1f: K rows: 0=w1[d0], 1=w1[d1], 2=b1, 3..15=0
            const int t = tid;
            const int lane = t & 31, kb = lane & 3;
            const int nn = ((t >> 5) & 7) * 8 + (lane >> 2);
            uint32_t b0 = 0;
            if (kb == 0) b0 = packh2(w1[e * 128 + nn], w1[e * 128 + 64 + nn]);
            else if (kb == 1) b0 = packh2(b1[e * 64 + nn], 0.f);
            d_w1f[e * 256 + t] = b0;
        }
        if (tid < 128) {  // w3f: N=8 padded, cols 0,1 = w3
            const int t = tid;
            const int ks = t >> 5, lane = t & 31;
            const int col = lane >> 2;
            const int k0 = ks * 16 + (lane & 3) * 2;
            uint2 v = make_uint2(0u, 0u);
            if (col < 2) {
                v.x = packh2(w3[e * 128 + k0 * 2 + col],
                             w3[e * 128 + (k0 + 1) * 2 + col]);
                v.y = packh2(w3[e * 128 + (k0 + 8) * 2 + col],
                             w3[e * 128 + (k0 + 9) * 2 + col]);
            }
            d_w3f[e * 128 + t] = v;
        }
    }
    __syncthreads();

    const float rw0 = rW[0], rw1 = rW[1], rw2 = rW[2], rw3 = rW[3];
    const float rw4 = rW[4], rw5 = rW[5], rw6 = rW[6], rw7 = rW[7];
    const float rb0 = rb[0], rb1 = rb[1], rb2 = rb[2], rb3 = rb[3];

    const int base = blockIdx.x * 512;
    const float4 xq = ((const float4*)x)[base / 2 + tid];
    const unsigned lane = tid & 31;

    int bests[2], wbs[2];
    #pragma unroll
    for (int s = 0; s < 2; s++) {
        const int i = base + 2 * tid + s;
        const float x0 = s ? xq.z : xq.x;
        const float x1 = s ? xq.w : xq.y;
        const float l0 = fmaf(x0, rw0, fmaf(x1, rw4, rb0));
        const float l1 = fmaf(x0, rw1, fmaf(x1, rw5, rb1));
        const float l2 = fmaf(x0, rw2, fmaf(x1, rw6, rb2));
        const float l3 = fmaf(x0, rw3, fmaf(x1, rw7, rb3));
        int best = 0; float bl = l0;
        if (l1 > bl) { bl = l1; best = 1; }
        if (l2 > bl) { bl = l2; best = 2; }
        if (l3 > bl) { bl = l3; best = 3; }
        ((float4*)(out + 2 * (size_t)n))[i] = make_float4(l0, l1, l2, l3);

        unsigned m[4];
        #pragma unroll
        for (int e = 0; e < 4; e++)
            m[e] = __ballot_sync(0xffffffffu, best == e);
        const unsigned mym = m[best];
        const int rank   = __popc(mym & ((1u << lane) - 1));
        const int leader = __ffs(mym) - 1;
        int wb = 0;
        if ((int)lane == leader) wb = atomicAdd(&scnt[best], __popc(mym));
        wb = __shfl_sync(0xffffffffu, wb, leader);
        bests[s] = best;
        wbs[s] = wb + rank;
    }
    __syncthreads();
    if (tid < 4) gbase[tid] = atomicAdd(&d_cnt[tid], scnt[tid]);
    __syncthreads();

    #pragma unroll
    for (int s = 0; s < 2; s++)
        d_perm[bests[s] * N_MAX + gbase[bests[s]] + wbs[s]] = base + 2 * tid + s;
}

// ---------------- Kernel 2: persistent CTAs, N-split warp pairs -----------
__global__ __launch_bounds__(256, 3)
void expert_kernel(const float* __restrict__ x,
                   const float* __restrict__ b2,
                   const float* __restrict__ b3,
                   float* __restrict__ out)
{
    __shared__ uint2    sW2f[1024];
    __shared__ uint32_t sW1f[256];
    __shared__ uint2    sW3f[128];
    __shared__ float2   sX[2][128];
    __shared__ int      sIdx[2][128];
    __shared__ float    sOp[128][2];     // odd-half L3 partials per row
    __shared__ float    sB2[64];
    __shared__ float    sB3[2];

    const int c0 = d_cnt[0], c1 = d_cnt[1], c2 = d_cnt[2], c3 = d_cnt[3];
    const int t0 = (c0 + TILE - 1) / TILE, t1 = (c1 + TILE - 1) / TILE;
    const int t2 = (c2 + TILE - 1) / TILE, t3 = (c3 + TILE - 1) / TILE;
    const int p1 = t0 + t1, p2 = p1 + t2, p3 = p2 + t3;

    const int chunk = (p3 + (int)gridDim.x - 1) / (int)gridDim.x;
    const int tstartb = blockIdx.x * chunk;
    int tend = tstartb + chunk;
    if (tend > p3) tend = p3;
    if (tstartb >= tend) return;

    const int tid = threadIdx.x;
    const int lane = tid & 31, wid = tid >> 5;
    const int pair = wid >> 1, half = wid & 1;
    const int qr = lane >> 2;
    const int kb = lane & 3;
    const int rbase = pair * 32 + qr;    // 4 pairs x 32 rows = 128
    const int jb = kb * 2;

    auto tmap = [&](int tile, int& e, int& lo, int& cnt) {
        if (tile < t0)      { e = 0; lo = tile;      cnt = c0; }
        else if (tile < p1) { e = 1; lo = tile - t0; cnt = c1; }
        else if (tile < p2) { e = 2; lo = tile - p1; cnt = c2; }
        else                { e = 3; lo = tile - p2; cnt = c3; }
    };

    // prefetch first tile's gather (threads 0-127)
    int pf_idx = 0;
    float2 pf_x = make_float2(0.f, 0.f);
    if (tid < TILE) {
        int e, lo, cnt; tmap(tstartb, e, lo, cnt);
        const int tok0 = lo * TILE;
        int mv = cnt - tok0; if (mv > TILE) mv = TILE;
        pf_idx = d_perm[e * N_MAX + tok0 + (tid < mv ? tid : 0)];
        pf_x = ((const float2*)x)[pf_idx];
    }

    int cur_e = -1;
    int buf = 0;

    for (int tile = tstartb; tile < tend; tile++, buf ^= 1) {
        int e, lo, cnt; tmap(tile, e, lo, cnt);

        if (e != cur_e) {
            if (cur_e >= 0) __syncthreads();
            cur_e = e;
            const uint4* g2 = (const uint4*)(d_w2f + e * 1024);
            #pragma unroll
            for (int t = tid; t < 512; t += 256) ((uint4*)sW2f)[t] = g2[t];
            if (tid < 64) ((uint4*)sW1f)[tid] = ((const uint4*)(d_w1f + e * 256))[tid];
            else if (tid < 128) ((uint4*)sW3f)[tid - 64] = ((const uint4*)(d_w3f + e * 128))[tid - 64];
            else if (tid < 192) sB2[tid - 128] = b2[e * 64 + (tid - 128)];
            if (tid < 2) sB3[tid] = b3[e * 2 + tid];
        }

        const int tok0 = lo * TILE;
        int mvalid = cnt - tok0;
        if (mvalid > TILE) mvalid = TILE;

        if (tid < TILE) {
            sIdx[buf][tid] = pf_idx;
            sX[buf][tid] = pf_x;
        }
        __syncthreads();

        // prefetch next tile (overlaps compute)
        if (tile + 1 < tend && tid < TILE) {
            int e2, lo2, cnt2; tmap(tile + 1, e2, lo2, cnt2);
            const int tk = lo2 * TILE;
            int mv2 = cnt2 - tk; if (mv2 > TILE) mv2 = TILE;
            pf_idx = d_perm[e2 * N_MAX + tk + (tid < mv2 ? tid : 0)];
            pf_x = ((const float2*)x)[pf_idx];
        }

        // --- X_ext A-frags (per pair rows) ---
        uint32_t xa[2][2];
        #pragma unroll
        for (int mt = 0; mt < 2; mt++) {
            const float2 v0 = sX[buf][rbase + mt * 16];
            const float2 v1 = sX[buf][rbase + mt * 16 + 8];
            uint32_t q0 = 0u, q1 = 0u;
            if (kb == 0)      { q0 = packh2(v0.x, v0.y); q1 = packh2(v1.x, v1.y); }
            else if (kb == 1) { q0 = 0x00003C00u;        q1 = 0x00003C00u; }
            xa[mt][0] = q0; xa[mt][1] = q1;
        }

        // --- L2 acc init = b2 (this warp's nt half) ---
        float acc[2][4][4];
        #pragma unroll
        for (int ntl = 0; ntl < 4; ntl++) {
            const int jg = (half * 4 + ntl) * 8 + jb;
            const float bj0 = sB2[jg], bj1 = sB2[jg + 1];
            #pragma unroll
            for (int mt = 0; mt < 2; mt++) {
                acc[mt][ntl][0] = bj0; acc[mt][ntl][1] = bj1;
                acc[mt][ntl][2] = bj0; acc[mt][ntl][3] = bj1;
            }
        }

        #pragma unroll
        for (int ks = 0; ks < 4; ks++) {
            const uint32_t Bw1a = sW1f[(2 * ks) * 32 + lane];
            const uint32_t Bw1b = sW1f[(2 * ks + 1) * 32 + lane];
            uint32_t A2[2][4];
            #pragma unroll
            for (int mt = 0; mt < 2; mt++) {
                uint32_t da[2] = {0u, 0u}, db[2] = {0u, 0u};
                mma_f16acc(da, xa[mt][0], xa[mt][1], Bw1a);
                mma_f16acc(db, xa[mt][0], xa[mt][1], Bw1b);
                A2[mt][0] = relu2(da[0]);
                A2[mt][1] = relu2(da[1]);
                A2[mt][2] = relu2(db[0]);
                A2[mt][3] = relu2(db[1]);
            }
            #pragma unroll
            for (int ntl = 0; ntl < 4; ntl++) {
                const uint2 B = sW2f[(ks * 8 + half * 4 + ntl) * 32 + lane];
                mma_f16(acc[0][ntl], A2[0][0], A2[0][1], A2[0][2], A2[0][3], B.x, B.y);
                mma_f16(acc[1][ntl], A2[1][0], A2[1][1], A2[1][2], A2[1][3], B.x, B.y);
            }
        }

        // --- L3 partial over this warp's 32 j's (K-tiles half*2 + {0,1}) ---
        float o[2][4];
        #pragma unroll
        for (int mt = 0; mt < 2; mt++)
            #pragma unroll
            for (int q = 0; q < 4; q++) o[mt][q] = 0.f;

        #pragma unroll
        for (int kt = 0; kt < 2; kt++) {
            const uint2 Bw3 = sW3f[(half * 2 + kt) * 32 + lane];
            #pragma unroll
            for (int mt = 0; mt < 2; mt++) {
                const uint32_t a0 = relu2(packh2(acc[mt][2 * kt][0],
                                                 acc[mt][2 * kt][1]));
                const uint32_t a1 = relu2(packh2(acc[mt][2 * kt][2],
                                                 acc[mt][2 * kt][3]));
                const uint32_t a2 = relu2(packh2(acc[mt][2 * kt + 1][0],
                                                 acc[mt][2 * kt + 1][1]));
                const uint32_t a3 = relu2(packh2(acc[mt][2 * kt + 1][2],
                                                 acc[mt][2 * kt + 1][3]));
                mma_f16(o[mt], a0, a1, a2, a3, Bw3.x, Bw3.y);
            }
        }

        // odd half publishes partials
        if (half == 1 && kb == 0) {
            #pragma unroll
            for (int mt = 0; mt < 2; mt++) {
                const int r0 = pair * 32 + mt * 16 + qr;
                sOp[r0][0] = o[mt][0];     sOp[r0][1] = o[mt][1];
                sOp[r0 + 8][0] = o[mt][2]; sOp[r0 + 8][1] = o[mt][3];
            }
        }
        __syncthreads();

        if (half == 0 && kb == 0) {
            const float b30 = sB3[0], b31 = sB3[1];
            #pragma unroll
            for (int mt = 0; mt < 2; mt++) {
                const int r0 = pair * 32 + mt * 16 + qr;
                if (r0 < mvalid)
                    ((float2*)out)[sIdx[buf][r0]] =
                        make_float2(o[mt][0] + sOp[r0][0] + b30,
                                    o[mt][1] + sOp[r0][1] + b31);
                const int r1 = r0 + 8;
                if (r1 < mvalid)
                    ((float2*)out)[sIdx[buf][r1]] =
                        make_float2(o[mt][2] + sOp[r1][0] + b30,
                                    o[mt][3] + sOp[r1][1] + b31);
            }
        }
        // next iteration uses the other sX buffer; its post-publish sync
        // separates any reuse. sOp reuse is separated by that same sync
        // (reads here precede it in program order).
    }
}

extern "C" void kernel_launch(void* const* d_in, const int* in_sizes, int n_in,
                              void* d_out, int out_size)
{
    const float* x  = (const float*)d_in[0];
    const float* rW = (const float*)d_in[1];
    const float* rb = (const float*)d_in[2];
    const float* w1 = (const float*)d_in[3];
    const float* b1 = (const float*)d_in[4];
    const float* w2 = (const float*)d_in[5];
    const float* b2 = (const float*)d_in[6];
    const float* w3 = (const float*)d_in[7];
    const float* b3 = (const float*)d_in[8];
    float* out = (float*)d_out;

    const int n_tok = in_sizes[0] / 2;

    void* cnt_addr = nullptr;
    cudaGetSymbolAddress(&cnt_addr, d_cnt);
    cudaMemsetAsync(cnt_addr, 0, 4 * sizeof(int));

    router_kernel<<<n_tok / 512, 256>>>(x, rW, rb, w1, b1, w2, w3, out, n_tok);

    expert_kernel<<<NBLK, 256>>>(x, b2, b3, out);
}

// round 15
// speedup vs baseline: 1.0343x; 1.0343x over previous
#include <cuda_runtime.h>
#include <cuda_fp16.h>
#include <cstdint>

// PolynomialMoE: N=1048576, DIM=2, HID=64, E=4, hard top-1.
// Output (float32): [ out (N*2) | router_logits (N*4) ]
//
// R15: single fused persistent kernel (router + global barrier + expert).
// R14 post-mortem: expert kernel converged (~41.5us, RF-limited at 16 warps
// x 128 regs); remaining win is the ~5us of router/memset/launch-gap
// overhead and cold-L2 gathers. 296 CTAs (2/SM x 148, co-residency
// guaranteed by __launch_bounds__(256,2)) route all tokens (blocks 0-7 also
// prep weight fragments), pass a generation-counter global barrier
// (monotonic -> graph-replay-safe), then run the R13 expert loop. Phase-2
// d_perm/x reads are L2-hot from phase 1. Math identical to R13.

typedef unsigned long long U64;

static constexpr int N_MAX = 1 << 20;
static constexpr int TILE  = 256;
static constexpr int NBLK  = 296;     // 2 CTAs/SM x 148 SMs (lower bound)

__device__ int d_cnt[4];
__device__ int d_perm[4 * N_MAX];
__device__ uint2    d_w2f[4 * 1024];  // [e][ks(4)][nt(8)][lane(32)]
__device__ uint32_t d_w1f[4 * 256];   // [e][nt(8)][lane(32)] (reg0 only)
__device__ uint2    d_w3f[4 * 128];   // [e][ks(4)][lane(32)]
__device__ unsigned d_bar;            // monotonic barrier counter

// ---------------- helpers ----------------
__device__ __forceinline__ uint32_t packh2(float lo, float hi) {
    uint32_t r;
    asm("cvt.rn.f16x2.f32 %0, %1, %2;" : "=r"(r) : "f"(hi), "f"(lo));
    return r;
}
__device__ __forceinline__ uint32_t relu2(uint32_t v) {
    uint32_t r;
    asm("max.f16x2 %0, %1, %2;" : "=r"(r) : "r"(v), "r"(0u));
    return r;
}
__device__ __forceinline__ void mma_f16(float c[4], uint32_t a0, uint32_t a1,
                                        uint32_t a2, uint32_t a3,
                                        uint32_t b0, uint32_t b1) {
    asm volatile(
        "mma.sync.aligned.m16n8k16.row.col.f32.f16.f16.f32 "
        "{%0,%1,%2,%3}, {%4,%5,%6,%7}, {%8,%9}, {%0,%1,%2,%3};"
        : "+f"(c[0]), "+f"(c[1]), "+f"(c[2]), "+f"(c[3])
        : "r"(a0), "r"(a1), "r"(a2), "r"(a3), "r"(b0), "r"(b1));
}
__device__ __forceinline__ void mma_f16acc(uint32_t c[2], uint32_t a0,
                                           uint32_t a1, uint32_t b0) {
    asm volatile(
        "mma.sync.aligned.m16n8k16.row.col.f16.f16.f16.f16 "
        "{%0,%1}, {%2,%3,%4,%5}, {%6,%7}, {%0,%1};"
        : "+r"(c[0]), "+r"(c[1])
        : "r"(a0), "r"(a1), "r"(0u), "r"(0u), "r"(b0), "r"(0u));
}

// generation-based global barrier: replay-safe (counter only grows).
__device__ __forceinline__ void global_barrier() {
    __syncthreads();
    if (threadIdx.x == 0) {
        __threadfence();                              // release phase-1 writes
        const unsigned gen = atomicAdd(&d_bar, 1u);
        const unsigned target = (gen / (unsigned)gridDim.x + 1u)
                                * (unsigned)gridDim.x;
        while (*(volatile unsigned*)&d_bar < target) {}
        __threadfence();                              // acquire
    }
    __syncthreads();
}

// ---------------- fused kernel ----------------
__global__ __launch_bounds__(256, 2)
void moe_fused(const float* __restrict__ x,
               const float* __restrict__ rW,
               const float* __restrict__ rb,
               const float* __restrict__ w1,
               const float* __restrict__ b1,
               const float* __restrict__ w2,
               const float* __restrict__ b2,
               const float* __restrict__ w3,
               const float* __restrict__ b3,
               float* __restrict__ out, int n)
{
    __shared__ uint2    sW2f[1024];
    __shared__ uint32_t sW1f[256];
    __shared__ uint2    sW3f[128];
    __shared__ float2   sX[2][256];
    __shared__ int      sIdx[2][256];
    __shared__ float    sB2[64];
    __shared__ float    sB3[2];
    __shared__ int      scnt[4], gbase[4];

    const int tid = threadIdx.x;

    // ============ phase 0: weight-fragment prep (blocks 0-7) ============
    if (blockIdx.x < 4) {
        const int e = blockIdx.x;
        #pragma unroll
        for (int t = tid; t < 1024; t += 256) {
            const int ks = t >> 8, nt = (t >> 5) & 7, lane = t & 31;
            const int k0 = ks * 16 + (lane & 3) * 2;
            const int nn = nt * 8 + (lane >> 2);
            d_w2f[e * 1024 + t] = make_uint2(
                packh2(w2[e * 4096 + k0 * 64 + nn],
                       w2[e * 4096 + (k0 + 1) * 64 + nn]),
                packh2(w2[e * 4096 + (k0 + 8) * 64 + nn],
                       w2[e * 4096 + (k0 + 9) * 64 + nn]));
        }
    } else if (blockIdx.x < 8) {
        const int e = blockIdx.x - 4;
        {   // w1f: K rows: 0=w1[d0], 1=w1[d1], 2=b1, 3..15=0
            const int lane = tid & 31, kb2 = lane & 3;
            const int nn = ((tid >> 5) & 7) * 8 + (lane >> 2);
            uint32_t v = 0;
            if (kb2 == 0) v = packh2(w1[e * 128 + nn], w1[e * 128 + 64 + nn]);
            else if (kb2 == 1) v = packh2(b1[e * 64 + nn], 0.f);
            d_w1f[e * 256 + tid] = v;
        }
        if (tid < 128) {  // w3f: N=8 padded, cols 0,1 = w3
            const int ks = tid >> 5, lane = tid & 31;
            const int col = lane >> 2;
            const int k0 = ks * 16 + (lane & 3) * 2;
            uint2 v = make_uint2(0u, 0u);
            if (col < 2) {
                v.x = packh2(w3[e * 128 + k0 * 2 + col],
                             w3[e * 128 + (k0 + 1) * 2 + col]);
                v.y = packh2(w3[e * 128 + (k0 + 8) * 2 + col],
                             w3[e * 128 + (k0 + 9) * 2 + col]);
            }
            d_w3f[e * 128 + tid] = v;
        }
    }

    // ============ phase 1: router (grid-stride, 2 tok/thread) ============
    {
        const float rw0 = rW[0], rw1 = rW[1], rw2 = rW[2], rw3 = rW[3];
        const float rw4 = rW[4], rw5 = rW[5], rw6 = rW[6], rw7 = rW[7];
        const float rb0 = rb[0], rb1 = rb[1], rb2 = rb[2], rb3 = rb[3];
        const unsigned lane = tid & 31;
        const int nchunks = n / 512;
        float* const logits = out + 2 * (size_t)n;

        for (int c = blockIdx.x; c < nchunks; c += gridDim.x) {
            if (tid < 4) scnt[tid] = 0;
            __syncthreads();

            const int base = c * 512;
            const float4 xq = ((const float4*)x)[base / 2 + tid];

            int bests[2], wbs[2];
            #pragma unroll
            for (int s = 0; s < 2; s++) {
                const int i = base + 2 * tid + s;
                const float x0 = s ? xq.z : xq.x;
                const float x1 = s ? xq.w : xq.y;
                const float l0 = fmaf(x0, rw0, fmaf(x1, rw4, rb0));
                const float l1 = fmaf(x0, rw1, fmaf(x1, rw5, rb1));
                const float l2 = fmaf(x0, rw2, fmaf(x1, rw6, rb2));
                const float l3 = fmaf(x0, rw3, fmaf(x1, rw7, rb3));
                int best = 0; float bl = l0;
                if (l1 > bl) { bl = l1; best = 1; }
                if (l2 > bl) { bl = l2; best = 2; }
                if (l3 > bl) { bl = l3; best = 3; }
                ((float4*)logits)[i] = make_float4(l0, l1, l2, l3);

                unsigned m[4];
                #pragma unroll
                for (int e = 0; e < 4; e++)
                    m[e] = __ballot_sync(0xffffffffu, best == e);
                const unsigned mym = m[best];
                const int rank   = __popc(mym & ((1u << lane) - 1));
                const int leader = __ffs(mym) - 1;
                int wb = 0;
                if ((int)lane == leader) wb = atomicAdd(&scnt[best], __popc(mym));
                wb = __shfl_sync(0xffffffffu, wb, leader);
                bests[s] = best;
                wbs[s] = wb + rank;
            }
            __syncthreads();
            if (tid < 4) gbase[tid] = atomicAdd(&d_cnt[tid], scnt[tid]);
            __syncthreads();

            #pragma unroll
            for (int s = 0; s < 2; s++)
                d_perm[bests[s] * N_MAX + gbase[bests[s]] + wbs[s]] =
                    base + 2 * tid + s;
        }
    }

    // ============ barrier: all routing + prep visible ============
    global_barrier();

    // ============ phase 2: expert tiles (R13 loop) ============
    const int c0 = d_cnt[0], c1 = d_cnt[1], c2 = d_cnt[2], c3 = d_cnt[3];
    const int t0 = (c0 + TILE - 1) / TILE, t1 = (c1 + TILE - 1) / TILE;
    const int t2 = (c2 + TILE - 1) / TILE, t3 = (c3 + TILE - 1) / TILE;
    const int p1 = t0 + t1, p2 = p1 + t2, p3 = p2 + t3;

    const int chunk = (p3 + (int)gridDim.x - 1) / (int)gridDim.x;
    const int tstartb = blockIdx.x * chunk;
    int tend = tstartb + chunk;
    if (tend > p3) tend = p3;
    if (tstartb >= tend) return;

    const int lane = tid & 31, wid = tid >> 5;
    const int qr = lane >> 2;
    const int kb = lane & 3;
    const int rbase = wid * 32 + qr;
    const int jb = kb * 2;

    auto tmap = [&](int tile, int& e, int& lo, int& cnt) {
        if (tile < t0)      { e = 0; lo = tile;      cnt = c0; }
        else if (tile < p1) { e = 1; lo = tile - t0; cnt = c1; }
        else if (tile < p2) { e = 2; lo = tile - p1; cnt = c2; }
        else                { e = 3; lo = tile - p2; cnt = c3; }
    };

    // prefetch first tile's gather
    int pf_idx;
    float2 pf_x;
    {
        int e, lo, cnt; tmap(tstartb, e, lo, cnt);
        const int tok0 = lo * TILE;
        int mv = cnt - tok0; if (mv > TILE) mv = TILE;
        pf_idx = d_perm[e * N_MAX + tok0 + (tid < mv ? tid : 0)];
        pf_x = ((const float2*)x)[pf_idx];
    }

    int cur_e = -1;
    int buf = 0;

    for (int tile = tstartb; tile < tend; tile++, buf ^= 1) {
        int e, lo, cnt; tmap(tile, e, lo, cnt);

        if (e != cur_e) {
            if (cur_e >= 0) __syncthreads();
            cur_e = e;
            const uint4* g2 = (const uint4*)(d_w2f + e * 1024);
            #pragma unroll
            for (int t = tid; t < 512; t += 256) ((uint4*)sW2f)[t] = g2[t];
            if (tid < 64) ((uint4*)sW1f)[tid] = ((const uint4*)(d_w1f + e * 256))[tid];
            else if (tid < 128) ((uint4*)sW3f)[tid - 64] = ((const uint4*)(d_w3f + e * 128))[tid - 64];
            else if (tid < 192) sB2[tid - 128] = b2[e * 64 + (tid - 128)];
            if (tid < 2) sB3[tid] = b3[e * 2 + tid];
        }

        const int tok0 = lo * TILE;
        int mvalid = cnt - tok0;
        if (mvalid > TILE) mvalid = TILE;

        sIdx[buf][tid] = pf_idx;
        sX[buf][tid] = pf_x;
        __syncthreads();

        // prefetch next tile (overlaps compute below)
        if (tile + 1 < tend) {
            int e2, lo2, cnt2; tmap(tile + 1, e2, lo2, cnt2);
            const int tk = lo2 * TILE;
            int mv2 = cnt2 - tk; if (mv2 > TILE) mv2 = TILE;
            pf_idx = d_perm[e2 * N_MAX + tk + (tid < mv2 ? tid : 0)];
            pf_x = ((const float2*)x)[pf_idx];
        }

        // --- X_ext A-frags ---
        uint32_t xa[2][2];
        #pragma unroll
        for (int mt = 0; mt < 2; mt++) {
            const float2 v0 = sX[buf][rbase + mt * 16];
            const float2 v1 = sX[buf][rbase + mt * 16 + 8];
            uint32_t q0 = 0u, q1 = 0u;
            if (kb == 0)      { q0 = packh2(v0.x, v0.y); q1 = packh2(v1.x, v1.y); }
            else if (kb == 1) { q0 = 0x00003C00u;        q1 = 0x00003C00u; }
            xa[mt][0] = q0; xa[mt][1] = q1;
        }

        // --- L2 acc init = b2 ---
        float acc[2][8][4];
        #pragma unroll
        for (int nt = 0; nt < 8; nt++) {
            const float bj0 = sB2[nt * 8 + jb], bj1 = sB2[nt * 8 + jb + 1];
            #pragma unroll
            for (int mt = 0; mt < 2; mt++) {
                acc[mt][nt][0] = bj0; acc[mt][nt][1] = bj1;
                acc[mt][nt][2] = bj0; acc[mt][nt][3] = bj1;
            }
        }

        #pragma unroll
        for (int ks = 0; ks < 4; ks++) {
            const uint32_t Bw1a = sW1f[(2 * ks) * 32 + lane];
            const uint32_t Bw1b = sW1f[(2 * ks + 1) * 32 + lane];
            uint32_t A2[2][4];
            #pragma unroll
            for (int mt = 0; mt < 2; mt++) {
                uint32_t da[2] = {0u, 0u}, db[2] = {0u, 0u};
                mma_f16acc(da, xa[mt][0], xa[mt][1], Bw1a);
                mma_f16acc(db, xa[mt][0], xa[mt][1], Bw1b);
                A2[mt][0] = relu2(da[0]);
                A2[mt][1] = relu2(da[1]);
                A2[mt][2] = relu2(db[0]);
                A2[mt][3] = relu2(db[1]);
            }
            #pragma unroll
            for (int nt = 0; nt < 8; nt++) {
                const uint2 B = sW2f[(ks * 8 + nt) * 32 + lane];
                mma_f16(acc[0][nt], A2[0][0], A2[0][1], A2[0][2], A2[0][3], B.x, B.y);
                mma_f16(acc[1][nt], A2[1][0], A2[1][1], A2[1][2], A2[1][3], B.x, B.y);
            }
        }

        // --- L3 as MMA ---
        float o[2][4];
        #pragma unroll
        for (int mt = 0; mt < 2; mt++)
            #pragma unroll
            for (int q = 0; q < 4; q++) o[mt][q] = 0.f;

        #pragma unroll
        for (int ks = 0; ks < 4; ks++) {
            const uint2 Bw3 = sW3f[ks * 32 + lane];
            #pragma unroll
            for (int mt = 0; mt < 2; mt++) {
                const uint32_t a0 = relu2(packh2(acc[mt][2 * ks][0],
                                                 acc[mt][2 * ks][1]));
                const uint32_t a1 = relu2(packh2(acc[mt][2 * ks][2],
                                                 acc[mt][2 * ks][3]));
                const uint32_t a2 = relu2(packh2(acc[mt][2 * ks + 1][0],
                                                 acc[mt][2 * ks + 1][1]));
                const uint32_t a3 = relu2(packh2(acc[mt][2 * ks + 1][2],
                                                 acc[mt][2 * ks + 1][3]));
                mma_f16(o[mt], a0, a1, a2, a3, Bw3.x, Bw3.y);
            }
        }

        if (kb == 0) {
            const float b30 = sB3[0], b31 = sB3[1];
            #pragma unroll
            for (int mt = 0; mt < 2; mt++) {
                const int r0 = rbase + mt * 16;
                if (r0 < mvalid)
                    ((float2*)out)[sIdx[buf][r0]] = make_float2(o[mt][0] + b30,
                                                                o[mt][1] + b31);
                const int r1 = r0 + 8;
                if (r1 < mvalid)
                    ((float2*)out)[sIdx[buf][r1]] = make_float2(o[mt][2] + b30,
                                                                o[mt][3] + b31);
            }
        }
        // next iteration writes the OTHER sX buffer; its post-publish sync
        // separates any reuse by a full tile.
    }
}

extern "C" void kernel_launch(void* const* d_in, const int* in_sizes, int n_in,
                              void* d_out, int out_size)
{
    const float* x  = (const float*)d_in[0];
    const float* rW = (const float*)d_in[1];
    const float* rb = (const float*)d_in[2];
    const float* w1 = (const float*)d_in[3];
    const float* b1 = (const float*)d_in[4];
    const float* w2 = (const float*)d_in[5];
    const float* b2 = (const float*)d_in[6];
    const float* w3 = (const float*)d_in[7];
    const float* b3 = (const float*)d_in[8];
    float* out = (float*)d_out;

    const int n_tok = in_sizes[0] / 2;

    void* cnt_addr = nullptr;
    cudaGetSymbolAddress(&cnt_addr, d_cnt);
    cudaMemsetAsync(cnt_addr, 0, 4 * sizeof(int));

    moe_fused<<<NBLK, 256>>>(x, rW, rb, w1, b1, w2, b2, w3, b3, out, n_tok);
}

// round 16
// speedup vs baseline: 1.1248x; 1.0875x over previous
#include <cuda_runtime.h>
#include <cuda_fp16.h>
#include <cstdint>

// PolynomialMoE: N=1048576, DIM=2, HID=64, E=4, hard top-1.
// Output (float32): [ out (N*2) | router_logits (N*4) ]
//
// R16: consolidation on the best-measured config (R11 two-kernel, expert
// byte-identical). R12-R15 structural variants all lost within noise.
// Router cuts: __match_any_sync replaces 4 ballots (issue-bound kernel),
// __stcs streaming stores for write-once logits/outputs keep d_perm/x/w2f
// L2-resident for the expert kernel's gathers.

typedef unsigned long long U64;

static constexpr int N_MAX = 1 << 20;
static constexpr int TILE  = 256;

__device__ int d_cnt[4];
__device__ int d_perm[4 * N_MAX];
__device__ uint2    d_w2f[4 * 1024];  // [e][ks(4)][nt(8)][lane(32)]
__device__ uint32_t d_w1f[4 * 256];   // [e][nt(8)][lane(32)] (reg0 only)
__device__ uint2    d_w3f[4 * 128];   // [e][ks(4)][lane(32)]

// ---------------- helpers ----------------
__device__ __forceinline__ uint32_t packh2(float lo, float hi) {
    uint32_t r;
    asm("cvt.rn.f16x2.f32 %0, %1, %2;" : "=r"(r) : "f"(hi), "f"(lo));
    return r;
}
__device__ __forceinline__ uint32_t relu2(uint32_t v) {
    uint32_t r;
    asm("max.f16x2 %0, %1, %2;" : "=r"(r) : "r"(v), "r"(0u));
    return r;
}
__device__ __forceinline__ void mma_f16(float c[4], uint32_t a0, uint32_t a1,
                                        uint32_t a2, uint32_t a3,
                                        uint32_t b0, uint32_t b1) {
    asm volatile(
        "mma.sync.aligned.m16n8k16.row.col.f32.f16.f16.f32 "
        "{%0,%1,%2,%3}, {%4,%5,%6,%7}, {%8,%9}, {%0,%1,%2,%3};"
        : "+f"(c[0]), "+f"(c[1]), "+f"(c[2]), "+f"(c[3])
        : "r"(a0), "r"(a1), "r"(a2), "r"(a3), "r"(b0), "r"(b1));
}
__device__ __forceinline__ void mma_f16acc(uint32_t c[2], uint32_t a0,
                                           uint32_t a1, uint32_t b0) {
    asm volatile(
        "mma.sync.aligned.m16n8k16.row.col.f16.f16.f16.f16 "
        "{%0,%1}, {%2,%3,%4,%5}, {%6,%7}, {%0,%1};"
        : "+r"(c[0]), "+r"(c[1])
        : "r"(a0), "r"(a1), "r"(0u), "r"(0u), "r"(b0), "r"(0u));
}

// ---------------- Kernel 1: router (match.any) + fused weight prep -------
__global__ __launch_bounds__(256)
void router_kernel(const float* __restrict__ x,
                   const float* __restrict__ rW,
                   const float* __restrict__ rb,
                   const float* __restrict__ w1,
                   const float* __restrict__ b1,
                   const float* __restrict__ w2,
                   const float* __restrict__ w3,
                   float* __restrict__ out, int n)
{
    __shared__ int scnt[4], gbase[4];
    const int tid = threadIdx.x;
    if (tid < 4) scnt[tid] = 0;

    if (blockIdx.x < 4) {
        // blocks 0-3: w2 fragments for expert e
        const int e = blockIdx.x;
        #pragma unroll
        for (int t = tid; t < 1024; t += 256) {
            const int ks = t >> 8, nt = (t >> 5) & 7, lane = t & 31;
            const int k0 = ks * 16 + (lane & 3) * 2;
            const int nn = nt * 8 + (lane >> 2);
            d_w2f[e * 1024 + t] = make_uint2(
                packh2(w2[e * 4096 + k0 * 64 + nn],
                       w2[e * 4096 + (k0 + 1) * 64 + nn]),
                packh2(w2[e * 4096 + (k0 + 8) * 64 + nn],
                       w2[e * 4096 + (k0 + 9) * 64 + nn]));
        }
    } else if (blockIdx.x < 8) {
        const int e = blockIdx.x - 4;
        {   // w1f: K rows: 0=w1[d0], 1=w1[d1], 2=b1, 3..15=0
            const int lane = tid & 31, kb2 = lane & 3;
            const int nn = ((tid >> 5) & 7) * 8 + (lane >> 2);
            uint32_t v = 0;
            if (kb2 == 0) v = packh2(w1[e * 128 + nn], w1[e * 128 + 64 + nn]);
            else if (kb2 == 1) v = packh2(b1[e * 64 + nn], 0.f);
            d_w1f[e * 256 + tid] = v;
        }
        if (tid < 128) {  // w3f: N=8 padded, cols 0,1 = w3
            const int ks = tid >> 5, lane = tid & 31;
            const int col = lane >> 2;
            const int k0 = ks * 16 + (lane & 3) * 2;
            uint2 v = make_uint2(0u, 0u);
            if (col < 2) {
                v.x = packh2(w3[e * 128 + k0 * 2 + col],
                             w3[e * 128 + (k0 + 1) * 2 + col]);
                v.y = packh2(w3[e * 128 + (k0 + 8) * 2 + col],
                             w3[e * 128 + (k0 + 9) * 2 + col]);
            }
            d_w3f[e * 128 + tid] = v;
        }
    }
    __syncthreads();

    const float rw0 = rW[0], rw1 = rW[1], rw2 = rW[2], rw3 = rW[3];
    const float rw4 = rW[4], rw5 = rW[5], rw6 = rW[6], rw7 = rW[7];
    const float rb0 = rb[0], rb1 = rb[1], rb2 = rb[2], rb3 = rb[3];

    const int base = blockIdx.x * 512;                // 2 tokens per thread
    const float4 xq = ((const float4*)x)[base / 2 + tid];
    const unsigned lane = tid & 31;
    const unsigned lt_mask = (1u << lane) - 1u;
    float4* const logits = (float4*)(out + 2 * (size_t)n);

    int bests[2], wbs[2];
    #pragma unroll
    for (int s = 0; s < 2; s++) {
        const int i = base + 2 * tid + s;
        const float x0 = s ? xq.z : xq.x;
        const float x1 = s ? xq.w : xq.y;
        const float l0 = fmaf(x0, rw0, fmaf(x1, rw4, rb0));
        const float l1 = fmaf(x0, rw1, fmaf(x1, rw5, rb1));
        const float l2 = fmaf(x0, rw2, fmaf(x1, rw6, rb2));
        const float l3 = fmaf(x0, rw3, fmaf(x1, rw7, rb3));
        int best = 0; float bl = l0;
        if (l1 > bl) { bl = l1; best = 1; }
        if (l2 > bl) { bl = l2; best = 2; }
        if (l3 > bl) { bl = l3; best = 3; }
        __stcs(&logits[i], make_float4(l0, l1, l2, l3));   // streaming store

        // one MATCH.ANY replaces 4 ballots
        const unsigned mym = __match_any_sync(0xffffffffu, best);
        const int rank   = __popc(mym & lt_mask);
        const int leader = __ffs(mym) - 1;
        int wb = 0;
        if ((int)lane == leader) wb = atomicAdd(&scnt[best], __popc(mym));
        wb = __shfl_sync(0xffffffffu, wb, leader);
        bests[s] = best;
        wbs[s] = wb + rank;
    }
    __syncthreads();
    if (tid < 4) gbase[tid] = atomicAdd(&d_cnt[tid], scnt[tid]);
    __syncthreads();

    #pragma unroll
    for (int s = 0; s < 2; s++)
        d_perm[bests[s] * N_MAX + gbase[bests[s]] + wbs[s]] = base + 2 * tid + s;
}

// ---------------- Kernel 2: expert tile (R11, byte-identical math) --------
__global__ __launch_bounds__(256, 2)
void expert_kernel(const float* __restrict__ x,
                   const float* __restrict__ b2,
                   const float* __restrict__ b3,
                   float* __restrict__ out)
{
    __shared__ uint2    sW2f[1024];
    __shared__ uint32_t sW1f[256];
    __shared__ uint2    sW3f[128];
    __shared__ float2   sX[256];
    __shared__ float    sB2[64];
    __shared__ float    sB3[2];
    __shared__ int      sIdx[256];

    // --- map blockIdx -> (expert, tile) ---
    const int c0 = d_cnt[0], c1 = d_cnt[1], c2 = d_cnt[2], c3 = d_cnt[3];
    const int t0 = (c0 + TILE - 1) / TILE, t1 = (c1 + TILE - 1) / TILE;
    const int t2 = (c2 + TILE - 1) / TILE, t3 = (c3 + TILE - 1) / TILE;
    int b = blockIdx.x, e, lo, cnt;
    if (b < t0)              { e = 0; lo = b; cnt = c0; }
    else if ((b -= t0) < t1) { e = 1; lo = b; cnt = c1; }
    else if ((b -= t1) < t2) { e = 2; lo = b; cnt = c2; }
    else if ((b -= t2) < t3) { e = 3; lo = b; cnt = c3; }
    else return;

    const int tid = threadIdx.x;
    const int tstart = lo * TILE;
    int mvalid = cnt - tstart;
    if (mvalid > TILE) mvalid = TILE;

    // --- stage ---
    {
        const uint4* g2 = (const uint4*)(d_w2f + e * 1024);
        #pragma unroll
        for (int t = tid; t < 512; t += 256) ((uint4*)sW2f)[t] = g2[t];
        if (tid < 64) ((uint4*)sW1f)[tid] = ((const uint4*)(d_w1f + e * 256))[tid];
        else if (tid < 128) ((uint4*)sW3f)[tid - 64] = ((const uint4*)(d_w3f + e * 128))[tid - 64];
        else if (tid < 192) {
            const int i = tid - 128;
            sB2[i] = b2[e * 64 + i];
        }
        if (tid < 2) sB3[tid] = b3[e * 2 + tid];
        const int token = d_perm[e * N_MAX + tstart + (tid < mvalid ? tid : 0)];
        sIdx[tid] = token;
        sX[tid] = ((const float2*)x)[token];
    }
    __syncthreads();

    const int lane = tid & 31, wid = tid >> 5;
    const int qr = lane >> 2;
    const int kb = lane & 3;
    const int rbase = wid * 32 + qr;
    const int jb = kb * 2;

    // --- X_ext A-fragments: cols 0,1 = x0,x1 (kb==0); col 2 = 1 (kb==1) ---
    uint32_t xa[2][2];
    #pragma unroll
    for (int mt = 0; mt < 2; mt++) {
        const float2 v0 = sX[rbase + mt * 16];
        const float2 v1 = sX[rbase + mt * 16 + 8];
        uint32_t p0 = 0u, p1 = 0u;
        if (kb == 0)      { p0 = packh2(v0.x, v0.y); p1 = packh2(v1.x, v1.y); }
        else if (kb == 1) { p0 = 0x00003C00u;        p1 = 0x00003C00u; }
        xa[mt][0] = p0; xa[mt][1] = p1;
    }

    // --- L2 acc init = b2 ---
    float acc[2][8][4];
    #pragma unroll
    for (int nt = 0; nt < 8; nt++) {
        const float bj0 = sB2[nt * 8 + jb], bj1 = sB2[nt * 8 + jb + 1];
        #pragma unroll
        for (int mt = 0; mt < 2; mt++) {
            acc[mt][nt][0] = bj0; acc[mt][nt][1] = bj1;
            acc[mt][nt][2] = bj0; acc[mt][nt][3] = bj1;
        }
    }

    #pragma unroll
    for (int ks = 0; ks < 4; ks++) {
        const uint32_t Bw1a = sW1f[(2 * ks) * 32 + lane];
        const uint32_t Bw1b = sW1f[(2 * ks + 1) * 32 + lane];
        uint32_t A2[2][4];
        #pragma unroll
        for (int mt = 0; mt < 2; mt++) {
            uint32_t da[2] = {0u, 0u}, db[2] = {0u, 0u};
            mma_f16acc(da, xa[mt][0], xa[mt][1], Bw1a);
            mma_f16acc(db, xa[mt][0], xa[mt][1], Bw1b);
            A2[mt][0] = relu2(da[0]);
            A2[mt][1] = relu2(da[1]);
            A2[mt][2] = relu2(db[0]);
            A2[mt][3] = relu2(db[1]);
        }
        #pragma unroll
        for (int nt = 0; nt < 8; nt++) {
            const uint2 B = sW2f[(ks * 8 + nt) * 32 + lane];
            mma_f16(acc[0][nt], A2[0][0], A2[0][1], A2[0][2], A2[0][3], B.x, B.y);
            mma_f16(acc[1][nt], A2[1][0], A2[1][1], A2[1][2], A2[1][3], B.x, B.y);
        }
    }

    // --- L3 as MMA: relu(acc) @ w3 (N=8 padded; cols 0,1 real) ---
    float o[2][4];
    #pragma unroll
    for (int mt = 0; mt < 2; mt++)
        #pragma unroll
        for (int q = 0; q < 4; q++) o[mt][q] = 0.f;

    #pragma unroll
    for (int ks = 0; ks < 4; ks++) {
        const uint2 Bw3 = sW3f[ks * 32 + lane];
        #pragma unroll
        for (int mt = 0; mt < 2; mt++) {
            const uint32_t a0 = relu2(packh2(acc[mt][2 * ks][0],
                                             acc[mt][2 * ks][1]));
            const uint32_t a1 = relu2(packh2(acc[mt][2 * ks][2],
                                             acc[mt][2 * ks][3]));
            const uint32_t a2 = relu2(packh2(acc[mt][2 * ks + 1][0],
                                             acc[mt][2 * ks + 1][1]));
            const uint32_t a3 = relu2(packh2(acc[mt][2 * ks + 1][2],
                                             acc[mt][2 * ks + 1][3]));
            mma_f16(o[mt], a0, a1, a2, a3, Bw3.x, Bw3.y);
        }
    }

    if (kb == 0) {   // these lanes hold output cols 0,1
        const float b30 = sB3[0], b31 = sB3[1];
        #pragma unroll
        for (int mt = 0; mt < 2; mt++) {
            const int r0 = rbase + mt * 16;
            if (r0 < mvalid)
                __stcs(&((float2*)out)[sIdx[r0]],
                       make_float2(o[mt][0] + b30, o[mt][1] + b31));
            const int r1 = r0 + 8;
            if (r1 < mvalid)
                __stcs(&((float2*)out)[sIdx[r1]],
                       make_float2(o[mt][2] + b30, o[mt][3] + b31));
        }
    }
}

extern "C" void kernel_launch(void* const* d_in, const int* in_sizes, int n_in,
                              void* d_out, int out_size)
{
    const float* x  = (const float*)d_in[0];
    const float* rW = (const float*)d_in[1];
    const float* rb = (const float*)d_in[2];
    const float* w1 = (const float*)d_in[3];
    const float* b1 = (const float*)d_in[4];
    const float* w2 = (const float*)d_in[5];
    const float* b2 = (const float*)d_in[6];
    const float* w3 = (const float*)d_in[7];
    const float* b3 = (const float*)d_in[8];
    float* out = (float*)d_out;

    const int n_tok = in_sizes[0] / 2;

    void* cnt_addr = nullptr;
    cudaGetSymbolAddress(&cnt_addr, d_cnt);
    cudaMemsetAsync(cnt_addr, 0, 4 * sizeof(int));

    router_kernel<<<n_tok / 512, 256>>>(x, rW, rb, w1, b1, w2, w3, out, n_tok);

    const int max_tiles = n_tok / TILE + 3;   // per-expert ceil slack
    expert_kernel<<<max_tiles, 256>>>(x, b2, b3, out);
}

// round 17
// speedup vs baseline: 1.2504x; 1.1116x over previous
#include <cuda_runtime.h>
#include <cuda_fp16.h>
#include <cstdint>

// PolynomialMoE: N=1048576, DIM=2, HID=64, E=4, hard top-1.
// Output (float32): [ out (N*2) | router_logits (N*4) ]
//
// R17: f16 accumulators for the L2 GEMM. Unlike R10/R14's occupancy pushes
// (which added traffic or work), this halves the accumulator register
// footprint (64 fp32 -> 32 packed f16) with IDENTICAL MMA count and
// traffic -> 3 CTAs/SM. Bonus: the f16-acc D-fragment is bit-identical to
// the L3 A-fragment, so the L3 A-build is just relu2 (16 packh2 deleted).
// b2 folded as packed-f16 acc init. Expected rel_err ~5-7e-4 (4 extra f16
// partial-sum roundings on top of the 3.24e-4 baseline); fp32-acc R11/R16
// at 47.1us is the fallback if this exceeds 1e-3.

typedef unsigned long long U64;

static constexpr int N_MAX = 1 << 20;
static constexpr int TILE  = 256;

__device__ int d_cnt[4];
__device__ int d_perm[4 * N_MAX];
__device__ uint2    d_w2f[4 * 1024];  // [e][ks(4)][nt(8)][lane(32)]
__device__ uint32_t d_w1f[4 * 256];   // [e][nt(8)][lane(32)] (reg0 only)
__device__ uint2    d_w3f[4 * 128];   // [e][ks(4)][lane(32)]

// ---------------- helpers ----------------
__device__ __forceinline__ uint32_t packh2(float lo, float hi) {
    uint32_t r;
    asm("cvt.rn.f16x2.f32 %0, %1, %2;" : "=r"(r) : "f"(hi), "f"(lo));
    return r;
}
__device__ __forceinline__ uint32_t relu2(uint32_t v) {
    uint32_t r;
    asm("max.f16x2 %0, %1, %2;" : "=r"(r) : "r"(v), "r"(0u));
    return r;
}
// f32-accumulator MMA
__device__ __forceinline__ void mma_f16(float c[4], uint32_t a0, uint32_t a1,
                                        uint32_t a2, uint32_t a3,
                                        uint32_t b0, uint32_t b1) {
    asm volatile(
        "mma.sync.aligned.m16n8k16.row.col.f32.f16.f16.f32 "
        "{%0,%1,%2,%3}, {%4,%5,%6,%7}, {%8,%9}, {%0,%1,%2,%3};"
        : "+f"(c[0]), "+f"(c[1]), "+f"(c[2]), "+f"(c[3])
        : "r"(a0), "r"(a1), "r"(a2), "r"(a3), "r"(b0), "r"(b1));
}
// f16-accumulator MMA, 2 A regs (a2=a3=0) — used by L1
__device__ __forceinline__ void mma_f16acc2(uint32_t c[2], uint32_t a0,
                                            uint32_t a1, uint32_t b0) {
    asm volatile(
        "mma.sync.aligned.m16n8k16.row.col.f16.f16.f16.f16 "
        "{%0,%1}, {%2,%3,%4,%5}, {%6,%7}, {%0,%1};"
        : "+r"(c[0]), "+r"(c[1])
        : "r"(a0), "r"(a1), "r"(0u), "r"(0u), "r"(b0), "r"(0u));
}
// f16-accumulator MMA, full 4 A regs — used by L2
__device__ __forceinline__ void mma_f16acc4(uint32_t c[2], uint32_t a0,
                                            uint32_t a1, uint32_t a2,
                                            uint32_t a3, uint32_t b0,
                                            uint32_t b1) {
    asm volatile(
        "mma.sync.aligned.m16n8k16.row.col.f16.f16.f16.f16 "
        "{%0,%1}, {%2,%3,%4,%5}, {%6,%7}, {%0,%1};"
        : "+r"(c[0]), "+r"(c[1])
        : "r"(a0), "r"(a1), "r"(a2), "r"(a3), "r"(b0), "r"(b1));
}

// ---------------- Kernel 1: router (match.any) + fused weight prep -------
__global__ __launch_bounds__(256)
void router_kernel(const float* __restrict__ x,
                   const float* __restrict__ rW,
                   const float* __restrict__ rb,
                   const float* __restrict__ w1,
                   const float* __restrict__ b1,
                   const float* __restrict__ w2,
                   const float* __restrict__ w3,
                   float* __restrict__ out, int n)
{
    __shared__ int scnt[4], gbase[4];
    const int tid = threadIdx.x;
    if (tid < 4) scnt[tid] = 0;

    if (blockIdx.x < 4) {
        const int e = blockIdx.x;
        #pragma unroll
        for (int t = tid; t < 1024; t += 256) {
            const int ks = t >> 8, nt = (t >> 5) & 7, lane = t & 31;
            const int k0 = ks * 16 + (lane & 3) * 2;
            const int nn = nt * 8 + (lane >> 2);
            d_w2f[e * 1024 + t] = make_uint2(
                packh2(w2[e * 4096 + k0 * 64 + nn],
                       w2[e * 4096 + (k0 + 1) * 64 + nn]),
                packh2(w2[e * 4096 + (k0 + 8) * 64 + nn],
                       w2[e * 4096 + (k0 + 9) * 64 + nn]));
        }
    } else if (blockIdx.x < 8) {
        const int e = blockIdx.x - 4;
        {   // w1f: K rows: 0=w1[d0], 1=w1[d1], 2=b1, 3..15=0
            const int lane = tid & 31, kb2 = lane & 3;
            const int nn = ((tid >> 5) & 7) * 8 + (lane >> 2);
            uint32_t v = 0;
            if (kb2 == 0) v = packh2(w1[e * 128 + nn], w1[e * 128 + 64 + nn]);
            else if (kb2 == 1) v = packh2(b1[e * 64 + nn], 0.f);
            d_w1f[e * 256 + tid] = v;
        }
        if (tid < 128) {  // w3f: N=8 padded, cols 0,1 = w3
            const int ks = tid >> 5, lane = tid & 31;
            const int col = lane >> 2;
            const int k0 = ks * 16 + (lane & 3) * 2;
            uint2 v = make_uint2(0u, 0u);
            if (col < 2) {
                v.x = packh2(w3[e * 128 + k0 * 2 + col],
                             w3[e * 128 + (k0 + 1) * 2 + col]);
                v.y = packh2(w3[e * 128 + (k0 + 8) * 2 + col],
                             w3[e * 128 + (k0 + 9) * 2 + col]);
            }
            d_w3f[e * 128 + tid] = v;
        }
    }
    __syncthreads();

    const float rw0 = rW[0], rw1 = rW[1], rw2 = rW[2], rw3 = rW[3];
    const float rw4 = rW[4], rw5 = rW[5], rw6 = rW[6], rw7 = rW[7];
    const float rb0 = rb[0], rb1 = rb[1], rb2 = rb[2], rb3 = rb[3];

    const int base = blockIdx.x * 512;                // 2 tokens per thread
    const float4 xq = ((const float4*)x)[base / 2 + tid];
    const unsigned lane = tid & 31;
    const unsigned lt_mask = (1u << lane) - 1u;
    float4* const logits = (float4*)(out + 2 * (size_t)n);

    int bests[2], wbs[2];
    #pragma unroll
    for (int s = 0; s < 2; s++) {
        const int i = base + 2 * tid + s;
        const float x0 = s ? xq.z : xq.x;
        const float x1 = s ? xq.w : xq.y;
        const float l0 = fmaf(x0, rw0, fmaf(x1, rw4, rb0));
        const float l1 = fmaf(x0, rw1, fmaf(x1, rw5, rb1));
        const float l2 = fmaf(x0, rw2, fmaf(x1, rw6, rb2));
        const float l3 = fmaf(x0, rw3, fmaf(x1, rw7, rb3));
        int best = 0; float bl = l0;
        if (l1 > bl) { bl = l1; best = 1; }
        if (l2 > bl) { bl = l2; best = 2; }
        if (l3 > bl) { bl = l3; best = 3; }
        __stcs(&logits[i], make_float4(l0, l1, l2, l3));

        const unsigned mym = __match_any_sync(0xffffffffu, best);
        const int rank   = __popc(mym & lt_mask);
        const int leader = __ffs(mym) - 1;
        int wb = 0;
        if ((int)lane == leader) wb = atomicAdd(&scnt[best], __popc(mym));
        wb = __shfl_sync(0xffffffffu, wb, leader);
        bests[s] = best;
        wbs[s] = wb + rank;
    }
    __syncthreads();
    if (tid < 4) gbase[tid] = atomicAdd(&d_cnt[tid], scnt[tid]);
    __syncthreads();

    #pragma unroll
    for (int s = 0; s < 2; s++)
        d_perm[bests[s] * N_MAX + gbase[bests[s]] + wbs[s]] = base + 2 * tid + s;
}

// ---------------- Kernel 2: expert tile (f16-acc L2, 3 CTAs/SM) -----------
__global__ __launch_bounds__(256, 3)
void expert_kernel(const float* __restrict__ x,
                   const float* __restrict__ b2,
                   const float* __restrict__ b3,
                   float* __restrict__ out)
{
    __shared__ uint2    sW2f[1024];
    __shared__ uint32_t sW1f[256];
    __shared__ uint2    sW3f[128];
    __shared__ float2   sX[256];
    __shared__ float    sB2[64];
    __shared__ float    sB3[2];
    __shared__ int      sIdx[256];

    // --- map blockIdx -> (expert, tile) ---
    const int c0 = d_cnt[0], c1 = d_cnt[1], c2 = d_cnt[2], c3 = d_cnt[3];
    const int t0 = (c0 + TILE - 1) / TILE, t1 = (c1 + TILE - 1) / TILE;
    const int t2 = (c2 + TILE - 1) / TILE, t3 = (c3 + TILE - 1) / TILE;
    int b = blockIdx.x, e, lo, cnt;
    if (b < t0)              { e = 0; lo = b; cnt = c0; }
    else if ((b -= t0) < t1) { e = 1; lo = b; cnt = c1; }
    else if ((b -= t1) < t2) { e = 2; lo = b; cnt = c2; }
    else if ((b -= t2) < t3) { e = 3; lo = b; cnt = c3; }
    else return;

    const int tid = threadIdx.x;
    const int tstart = lo * TILE;
    int mvalid = cnt - tstart;
    if (mvalid > TILE) mvalid = TILE;

    // --- stage ---
    {
        const uint4* g2 = (const uint4*)(d_w2f + e * 1024);
        #pragma unroll
        for (int t = tid; t < 512; t += 256) ((uint4*)sW2f)[t] = g2[t];
        if (tid < 64) ((uint4*)sW1f)[tid] = ((const uint4*)(d_w1f + e * 256))[tid];
        else if (tid < 128) ((uint4*)sW3f)[tid - 64] = ((const uint4*)(d_w3f + e * 128))[tid - 64];
        else if (tid < 192) {
            const int i = tid - 128;
            sB2[i] = b2[e * 64 + i];
        }
        if (tid < 2) sB3[tid] = b3[e * 2 + tid];
        const int token = d_perm[e * N_MAX + tstart + (tid < mvalid ? tid : 0)];
        sIdx[tid] = token;
        sX[tid] = ((const float2*)x)[token];
    }
    __syncthreads();

    const int lane = tid & 31, wid = tid >> 5;
    const int qr = lane >> 2;
    const int kb = lane & 3;
    const int rbase = wid * 32 + qr;
    const int jb = kb * 2;

    // --- X_ext A-fragments: cols 0,1 = x0,x1 (kb==0); col 2 = 1 (kb==1) ---
    uint32_t xa[2][2];
    #pragma unroll
    for (int mt = 0; mt < 2; mt++) {
        const float2 v0 = sX[rbase + mt * 16];
        const float2 v1 = sX[rbase + mt * 16 + 8];
        uint32_t p0 = 0u, p1 = 0u;
        if (kb == 0)      { p0 = packh2(v0.x, v0.y); p1 = packh2(v1.x, v1.y); }
        else if (kb == 1) { p0 = 0x00003C00u;        p1 = 0x00003C00u; }
        xa[mt][0] = p0; xa[mt][1] = p1;
    }

    // --- L2 acc (packed f16) init = b2 ---
    uint32_t accp[2][8][2];
    #pragma unroll
    for (int nt = 0; nt < 8; nt++) {
        const uint32_t bj = packh2(sB2[nt * 8 + jb], sB2[nt * 8 + jb + 1]);
        #pragma unroll
        for (int mt = 0; mt < 2; mt++) {
            accp[mt][nt][0] = bj;
            accp[mt][nt][1] = bj;
        }
    }

    #pragma unroll
    for (int ks = 0; ks < 4; ks++) {
        const uint32_t Bw1a = sW1f[(2 * ks) * 32 + lane];
        const uint32_t Bw1b = sW1f[(2 * ks + 1) * 32 + lane];
        uint32_t A2[2][4];
        #pragma unroll
        for (int mt = 0; mt < 2; mt++) {
            uint32_t da[2] = {0u, 0u}, db[2] = {0u, 0u};
            mma_f16acc2(da, xa[mt][0], xa[mt][1], Bw1a);
            mma_f16acc2(db, xa[mt][0], xa[mt][1], Bw1b);
            A2[mt][0] = relu2(da[0]);
            A2[mt][1] = relu2(da[1]);
            A2[mt][2] = relu2(db[0]);
            A2[mt][3] = relu2(db[1]);
        }
        #pragma unroll
        for (int nt = 0; nt < 8; nt++) {
            const uint2 B = sW2f[(ks * 8 + nt) * 32 + lane];
            mma_f16acc4(accp[0][nt], A2[0][0], A2[0][1], A2[0][2], A2[0][3],
                        B.x, B.y);
            mma_f16acc4(accp[1][nt], A2[1][0], A2[1][1], A2[1][2], A2[1][3],
                        B.x, B.y);
        }
    }

    // --- L3 as MMA: A-frags are the relu'd acc regs directly ---
    float o[2][4];
    #pragma unroll
    for (int mt = 0; mt < 2; mt++)
        #pragma unroll
        for (int q = 0; q < 4; q++) o[mt][q] = 0.f;

    #pragma unroll
    for (int ks = 0; ks < 4; ks++) {
        const uint2 Bw3 = sW3f[ks * 32 + lane];
        #pragma unroll
        for (int mt = 0; mt < 2; mt++) {
            mma_f16(o[mt],
                    relu2(accp[mt][2 * ks][0]),
                    relu2(accp[mt][2 * ks][1]),
                    relu2(accp[mt][2 * ks + 1][0]),
                    relu2(accp[mt][2 * ks + 1][1]),
                    Bw3.x, Bw3.y);
        }
    }

    if (kb == 0) {   // these lanes hold output cols 0,1
        const float b30 = sB3[0], b31 = sB3[1];
        #pragma unroll
        for (int mt = 0; mt < 2; mt++) {
            const int r0 = rbase + mt * 16;
            if (r0 < mvalid)
                __stcs(&((float2*)out)[sIdx[r0]],
                       make_float2(o[mt][0] + b30, o[mt][1] + b31));
            const int r1 = r0 + 8;
            if (r1 < mvalid)
                __stcs(&((float2*)out)[sIdx[r1]],
                       make_float2(o[mt][2] + b30, o[mt][3] + b31));
        }
    }
}

extern "C" void kernel_launch(void* const* d_in, const int* in_sizes, int n_in,
                              void* d_out, int out_size)
{
    const float* x  = (const float*)d_in[0];
    const float* rW = (const float*)d_in[1];
    const float* rb = (const float*)d_in[2];
    const float* w1 = (const float*)d_in[3];
    const float* b1 = (const float*)d_in[4];
    const float* w2 = (const float*)d_in[5];
    const float* b2 = (const float*)d_in[6];
    const float* w3 = (const float*)d_in[7];
    const float* b3 = (const float*)d_in[8];
    float* out = (float*)d_out;

    const int n_tok = in_sizes[0] / 2;

    void* cnt_addr = nullptr;
    cudaGetSymbolAddress(&cnt_addr, d_cnt);
    cudaMemsetAsync(cnt_addr, 0, 4 * sizeof(int));

    router_kernel<<<n_tok / 512, 256>>>(x, rW, rb, w1, b1, w2, w3, out, n_tok);

    const int max_tiles = n_tok / TILE + 3;   // per-expert ceil slack
    expert_kernel<<<max_tiles, 256>>>(x, b2, b3, out);
}